// round 14
// baseline (speedup 1.0000x reference)
#include <cuda_runtime.h>
#include <math.h>

#define BATCH   8
#define SEQ     1024
#define IN_DIM  64
#define D_MODEL 256
#define D_INNER 512
#define D_STATE 16
#define D_CONV  4
#define DT_RANK 16
#define N_LAYERS 4
#define BL (BATCH*SEQ)            // 8192 rows
#define XD_KZ 8                   // split-K factor for x_dbl
#define NC    32                  // time chunks for scan
#define CHUNK (SEQ/NC)            // 32

// ---------------- scratch (static device globals; no runtime alloc) --------
__device__ float g_h   [BL * D_MODEL];
__device__ float g_xz  [BL * 2 * D_INNER];
__device__ float g_xc  [BL * D_INNER];
__device__ float g_xdbl[BL * 48];
__device__ float g_xdp [XD_KZ * BL * 48];
__device__ float g_dt  [BL * D_INNER];
__device__ float g_y   [BL * D_INNER];
__device__ float g_ob  [BL * D_MODEL];
__device__ float g_P   [BATCH * NC * D_INNER * D_STATE];
__device__ float g_q   [BATCH * NC * D_INNER * D_STATE];
__device__ float g_hin [BATCH * NC * D_INNER * D_STATE];

// ---------------- f32x2 helpers --------------------------------------------
__device__ __forceinline__ unsigned long long pk2dup(float a) {
    unsigned long long r;
    asm("mov.b64 %0, {%1, %1};" : "=l"(r) : "f"(a));
    return r;
}
__device__ __forceinline__ void fma2(unsigned long long& d,
                                     unsigned long long a, unsigned long long b) {
    asm("fma.rn.f32x2 %0, %1, %2, %0;" : "+l"(d) : "l"(a), "l"(b));
}
__device__ __forceinline__ float2 up2(unsigned long long v) {
    float2 o;
    asm("mov.b64 {%0, %1}, %2;" : "=f"(o.x), "=f"(o.y) : "l"(v));
    return o;
}

// ---------------- tf32 helpers ----------------------------------------------
__device__ __forceinline__ unsigned f2tf(float x) {
    unsigned r;
    asm("cvt.rna.tf32.f32 %0, %1;" : "=r"(r) : "f"(x));
    return r;
}
__device__ __forceinline__ void mma_tf32(float* c, const unsigned* a,
                                         const unsigned* b) {
    asm("mma.sync.aligned.m16n8k8.row.col.f32.tf32.tf32.f32 "
        "{%0,%1,%2,%3}, {%4,%5,%6,%7}, {%8,%9}, {%0,%1,%2,%3};"
        : "+f"(c[0]), "+f"(c[1]), "+f"(c[2]), "+f"(c[3])
        : "r"(a[0]), "r"(a[1]), "r"(a[2]), "r"(a[3]), "r"(b[0]), "r"(b[1]));
}

// ============================================================================
// Tensor-core NT GEMM, 4-warp (round-9 proven): BM=128 BN=64 BK=16.
// ============================================================================
template<bool BIAS>
__global__ void __launch_bounds__(128, 3)
gemm_tc_kernel(const float* __restrict__ A, int lda,
               const float* __restrict__ B, int ldb,
               const float* __restrict__ bias,
               float* __restrict__ C, int ldc,
               int M, int N, int K)
{
    constexpr int BM = 128, BN = 64, BK = 16, PAD = 4;

    __shared__ __align__(16) unsigned As[2][BM][BK + PAD];
    __shared__ __align__(16) unsigned Bs[2][BN][BK + PAD];

    const int tid  = threadIdx.x;
    const int lane = tid & 31;
    const int wid  = tid >> 5;
    const int g    = lane >> 2;
    const int tg   = lane & 3;
    const int mw   = (wid >> 1) * 64;
    const int nw   = (wid & 1) * 32;
    const int m0   = blockIdx.y * BM;
    const int n0   = blockIdx.x * BN;

    float acc[4][4][4];
    #pragma unroll
    for (int i = 0; i < 4; i++)
        #pragma unroll
        for (int j = 0; j < 4; j++)
            #pragma unroll
            for (int f = 0; f < 4; f++) acc[i][j][f] = 0.f;

    float4 vA[4], vB[2];

    auto loadA = [&](int k0) {
        #pragma unroll
        for (int i = 0; i < 4; i++) {
            int idx = tid + i * 128;
            int r = idx >> 2, cq = idx & 3;
            vA[i] = *(const float4*)&A[(long)(m0 + r) * lda + k0 + cq*4];
        }
    };
    auto loadB = [&](int k0) {
        #pragma unroll
        for (int i = 0; i < 2; i++) {
            int idx = tid + i * 128;
            int r = idx >> 2, cq = idx & 3;
            vB[i] = *(const float4*)&B[(long)(n0 + r) * ldb + k0 + cq*4];
        }
    };
    auto stage = [&](int s) {
        #pragma unroll
        for (int i = 0; i < 4; i++) {
            int idx = tid + i * 128;
            int r = idx >> 2, cq = idx & 3;
            uint4 t = make_uint4(f2tf(vA[i].x), f2tf(vA[i].y),
                                 f2tf(vA[i].z), f2tf(vA[i].w));
            *(uint4*)&As[s][r][cq*4] = t;
        }
        #pragma unroll
        for (int i = 0; i < 2; i++) {
            int idx = tid + i * 128;
            int r = idx >> 2, cq = idx & 3;
            uint4 t = make_uint4(f2tf(vB[i].x), f2tf(vB[i].y),
                                 f2tf(vB[i].z), f2tf(vB[i].w));
            *(uint4*)&Bs[s][r][cq*4] = t;
        }
    };

    loadA(0); loadB(0); stage(0);
    __syncthreads();

    int s = 0;
    for (int k0 = 0; k0 < K; k0 += BK) {
        bool has_next = (k0 + BK) < K;
        if (has_next) { loadA(k0 + BK); loadB(k0 + BK); }

        #pragma unroll
        for (int ks = 0; ks < BK; ks += 8) {
            unsigned a[4][4], b[4][2];
            #pragma unroll
            for (int mt = 0; mt < 4; mt++) {
                int rb = mw + mt * 16;
                a[mt][0] = As[s][rb + g    ][ks + tg    ];
                a[mt][1] = As[s][rb + g + 8][ks + tg    ];
                a[mt][2] = As[s][rb + g    ][ks + tg + 4];
                a[mt][3] = As[s][rb + g + 8][ks + tg + 4];
            }
            #pragma unroll
            for (int nt = 0; nt < 4; nt++) {
                int nb = nw + nt * 8;
                b[nt][0] = Bs[s][nb + g][ks + tg    ];
                b[nt][1] = Bs[s][nb + g][ks + tg + 4];
            }
            #pragma unroll
            for (int mt = 0; mt < 4; mt++)
                #pragma unroll
                for (int nt = 0; nt < 4; nt++)
                    mma_tf32(acc[mt][nt], a[mt], b[nt]);
        }

        if (has_next) {
            stage(s ^ 1);
            __syncthreads();
            s ^= 1;
        }
    }

    #pragma unroll
    for (int mt = 0; mt < 4; mt++) {
        #pragma unroll
        for (int nt = 0; nt < 4; nt++) {
            int m = m0 + mw + mt * 16 + g;
            int n = n0 + nw + nt * 8 + 2 * tg;
            float2 v0 = make_float2(acc[mt][nt][0], acc[mt][nt][1]);
            float2 v1 = make_float2(acc[mt][nt][2], acc[mt][nt][3]);
            if (BIAS) {
                float b0 = bias[n], b1 = bias[n+1];
                v0.x += b0;  v0.y += b1;
                v1.x += b0;  v1.y += b1;
            }
            *(float2*)&C[(long)m * ldc + n]       = v0;
            *(float2*)&C[(long)(m+8) * ldc + n]   = v1;
        }
    }
}

// ---------------- f32x2 GEMM (x_dbl split-K path, proven config) ------------
template<int BM, int BN, int BK, int TM, int TN, bool NG, bool SPLIT, int OCC>
__global__ void __launch_bounds__((BM/TM)*(BN/TN), OCC)
gemm4_kernel(const float* __restrict__ A, int lda,
             const float* __restrict__ B, int ldb,
             const float* __restrict__ bias,
             float* __restrict__ C, int ldc,
             int M, int N, int K)
{
    constexpr int THREADS = (BM/TM)*(BN/TN);
    constexpr int LAV = (BM*BK)/(4*THREADS);
    constexpr int LBV = (BN*BK)/(4*THREADS);
    static_assert(LAV >= 1 && LBV >= 1, "tile too small");

    if (SPLIT) {
        int z = blockIdx.z;
        A += (long)z * K;
        B += (long)z * K;
        C += (long)z * M * ldc;
    }

    __shared__ __align__(16) float As[2][BK][BM];
    __shared__ __align__(16) float Bs[2][BK][BN];

    const int tid = threadIdx.x;
    const int tx  = tid % (BN/TN);
    const int ty  = tid / (BN/TN);
    const int m0  = blockIdx.y * BM;
    const int n0  = blockIdx.x * BN;

    unsigned long long acc[TM][TN/2];
    #pragma unroll
    for (int i = 0; i < TM; i++)
        #pragma unroll
        for (int j = 0; j < TN/2; j++) acc[i][j] = 0ull;

    float4 vA[LAV], vB[LBV];

    auto loadA = [&](int k0) {
        #pragma unroll
        for (int i = 0; i < LAV; i++) {
            int idx = tid + i * THREADS;
            int r = idx / (BK/4), cq = idx % (BK/4);
            vA[i] = *(const float4*)&A[(long)(m0 + r) * lda + k0 + cq*4];
        }
    };
    auto loadB = [&](int k0) {
        #pragma unroll
        for (int i = 0; i < LBV; i++) {
            int idx = tid + i * THREADS;
            int r = idx / (BK/4), cq = idx % (BK/4);
            if (!NG || (n0 + r) < N)
                vB[i] = *(const float4*)&B[(long)(n0 + r) * ldb + k0 + cq*4];
            else
                vB[i] = make_float4(0.f, 0.f, 0.f, 0.f);
        }
    };
    auto stage = [&](int s) {
        #pragma unroll
        for (int i = 0; i < LAV; i++) {
            int idx = tid + i * THREADS;
            int r = idx / (BK/4), cq = idx % (BK/4);
            As[s][cq*4+0][r] = vA[i].x;  As[s][cq*4+1][r] = vA[i].y;
            As[s][cq*4+2][r] = vA[i].z;  As[s][cq*4+3][r] = vA[i].w;
        }
        #pragma unroll
        for (int i = 0; i < LBV; i++) {
            int idx = tid + i * THREADS;
            int r = idx / (BK/4), cq = idx % (BK/4);
            Bs[s][cq*4+0][r] = vB[i].x;  Bs[s][cq*4+1][r] = vB[i].y;
            Bs[s][cq*4+2][r] = vB[i].z;  Bs[s][cq*4+3][r] = vB[i].w;
        }
    };

    loadA(0); loadB(0); stage(0);
    __syncthreads();

    int s = 0;
    for (int k0 = 0; k0 < K; k0 += BK) {
        bool has_next = (k0 + BK) < K;
        if (has_next) { loadA(k0 + BK); loadB(k0 + BK); }

        #pragma unroll
        for (int kk = 0; kk < BK; kk++) {
            float a[TM];
            #pragma unroll
            for (int i = 0; i < TM; i += 4)
                *(float4*)&a[i] = *(const float4*)&As[s][kk][ty*TM + i];
            unsigned long long a2[TM];
            #pragma unroll
            for (int i = 0; i < TM; i++) a2[i] = pk2dup(a[i]);

            unsigned long long b2[TN/2];
            #pragma unroll
            for (int j = 0; j < TN/2; j += 2) {
                ulonglong2 tv = *(const ulonglong2*)&Bs[s][kk][tx*TN + 2*j];
                b2[j] = tv.x;  b2[j+1] = tv.y;
            }

            #pragma unroll
            for (int i = 0; i < TM; i++)
                #pragma unroll
                for (int j = 0; j < TN/2; j++)
                    fma2(acc[i][j], a2[i], b2[j]);
        }

        if (has_next) {
            stage(s ^ 1);
            __syncthreads();
            s ^= 1;
        }
    }

    #pragma unroll
    for (int i = 0; i < TM; i++) {
        int m = m0 + ty*TM + i;
        #pragma unroll
        for (int j = 0; j < TN/2; j++) {
            float2 v = up2(acc[i][j]);
            int n = n0 + tx*TN + 2*j;
            float x0 = v.x, x1 = v.y;
            if (bias) {
                if (!NG || n   < N) x0 += bias[n];
                if (!NG || n+1 < N) x1 += bias[n+1];
            }
            if (!NG || n   < N) C[(long)m*ldc + n  ] = x0;
            if (!NG || n+1 < N) C[(long)m*ldc + n+1] = x1;
        }
    }
}

// ---------------- split-K partial sum (XD_KZ -> 1), float4 ------------------
__global__ void __launch_bounds__(256)
reduceK_kernel(const float* __restrict__ in, float* __restrict__ out, int n)
{
    int i = (blockIdx.x * 256 + threadIdx.x) * 4;
    if (i >= n) return;
    float4 acc = make_float4(0.f, 0.f, 0.f, 0.f);
    #pragma unroll
    for (int z = 0; z < XD_KZ; z++) {
        float4 v = *(const float4*)&in[(long)z * n + i];
        acc.x += v.x;  acc.y += v.y;  acc.z += v.z;  acc.w += v.w;
    }
    *(float4*)&out[i] = acc;
}

// ---------------- causal depthwise conv (D_CONV=4) + SiLU, float4 ----------
__global__ void __launch_bounds__(256)
conv_silu_kernel(const float* __restrict__ xz,
                 const float* __restrict__ cw,
                 const float* __restrict__ cb,
                 float* __restrict__ xc)
{
    int idx = blockIdx.x * 256 + threadIdx.x;
    int dq = idx & 127;
    int bl = idx >> 7;
    int l  = bl & (SEQ - 1);
    int b0 = bl - l;
    int d  = dq * 4;

    float4 w0 = __ldg((const float4*)&cw[(d+0)*D_CONV]);
    float4 w1 = __ldg((const float4*)&cw[(d+1)*D_CONV]);
    float4 w2 = __ldg((const float4*)&cw[(d+2)*D_CONV]);
    float4 w3 = __ldg((const float4*)&cw[(d+3)*D_CONV]);
    float4 bv = __ldg((const float4*)&cb[d]);

    float a0 = bv.x, a1 = bv.y, a2 = bv.z, a3 = bv.w;
    #pragma unroll
    for (int k = 0; k < D_CONV; k++) {
        int ls = l - (D_CONV - 1) + k;
        if (ls >= 0) {
            float4 xv = __ldg((const float4*)&xz[(long)(b0+ls)*(2*D_INNER) + d]);
            a0 = fmaf(xv.x, (&w0.x)[k], a0);
            a1 = fmaf(xv.y, (&w1.x)[k], a1);
            a2 = fmaf(xv.z, (&w2.x)[k], a2);
            a3 = fmaf(xv.w, (&w3.x)[k], a3);
        }
    }
    float4 o;
    o.x = a0 / (1.f + __expf(-a0));
    o.y = a1 / (1.f + __expf(-a1));
    o.z = a2 / (1.f + __expf(-a2));
    o.w = a3 / (1.f + __expf(-a3));
    *(float4*)&xc[(long)bl * D_INNER + d] = o;
}

// ============================================================================
// Chunked selective scan (round-9 proven form), NC=32 chunks of 32 steps.
// One thread per channel; phase A stores dt, phase C loads it.
// ============================================================================

__device__ __forceinline__ void da_tree(float r, float* da)
{
    float r2  = r * r;
    float r4  = r2 * r2;
    float r8  = r4 * r4;
    float r12 = r8 * r4;
    float g0 = r, g1 = r2, g2 = r2 * r, g3 = r4;
    da[0] = g0;        da[1] = g1;        da[2] = g2;        da[3] = g3;
    da[4] = g0 * r4;   da[5] = g1 * r4;   da[6] = g2 * r4;   da[7] = g3 * r4;
    da[8] = g0 * r8;   da[9] = g1 * r8;   da[10] = g2 * r8;  da[11] = g3 * r8;
    da[12] = g0 * r12; da[13] = g1 * r12; da[14] = g2 * r12; da[15] = g3 * r12;
}

struct ChCtx {
    int b, d;
    float bdt, Dval;
    float4 w[4];
    float Av[16];
    long sumIdx;
    bool fast;
};

__device__ __forceinline__ ChCtx ch_setup(
    const float* A_log, const float* Dp,
    const float* W_dt, const float* b_dt, int chunk)
{
    ChCtx cx;
    cx.d = blockIdx.x * 128 + threadIdx.x;
    cx.b = blockIdx.y;
    bool ok = true;
    #pragma unroll
    for (int n = 0; n < 16; n++) {
        cx.Av[n] = -__expf(A_log[cx.d*D_STATE + n]);
        ok = ok && (fabsf(cx.Av[n] + (float)(n+1)) <= 1e-5f * (n+1));
    }
    cx.fast = __all_sync(0xffffffffu, ok);
    cx.Dval = Dp[cx.d];
    cx.bdt  = __ldg(&b_dt[cx.d]);
    #pragma unroll
    for (int i = 0; i < 4; i++)
        cx.w[i] = __ldg((const float4*)&W_dt[cx.d*DT_RANK + i*4]);
    cx.sumIdx = (((long)cx.b*NC + chunk)*D_INNER + cx.d)*16;
    return cx;
}

__device__ __forceinline__ float dot16_sp(const float* row, const ChCtx& cx)
{
    float s = cx.bdt;
    #pragma unroll
    for (int i = 0; i < 4; i++) {
        float4 dq = __ldg((const float4*)(row + i*4));
        s = fmaf(dq.x, cx.w[i].x, s);
        s = fmaf(dq.y, cx.w[i].y, s);
        s = fmaf(dq.z, cx.w[i].z, s);
        s = fmaf(dq.w, cx.w[i].w, s);
    }
    return (s > 20.f) ? s : __logf(1.f + __expf(s));
}

template<bool FAST>
__device__ __forceinline__ void phaseA_body(
    const ChCtx& cx, const float* pbc, const float* pxc, float* pdt,
    int t0, float* P, float* Q)
{
    float Pr[16], Qr[16];
    #pragma unroll
    for (int n = 0; n < 16; n++) { Pr[n] = 1.f; Qr[n] = 0.f; }

    #pragma unroll 2
    for (int t = t0; t < t0 + CHUNK; t++) {
        const float* row = pbc + (long)t * 48;
        float xcv = __ldg(pxc + (long)t * D_INNER);
        float dtv = dot16_sp(row, cx);
        pdt[(long)t * D_INNER] = dtv;

        float da[16];
        if (FAST) da_tree(__expf(-dtv), da);
        else {
            #pragma unroll
            for (int n = 0; n < 16; n++) da[n] = __expf(dtv * cx.Av[n]);
        }

        float u = dtv * xcv;
        #pragma unroll
        for (int i = 0; i < 4; i++) {
            float4 Bv = __ldg((const float4*)(row + 16 + i*4));
            Qr[i*4+0] = fmaf(da[i*4+0], Qr[i*4+0], u * Bv.x);
            Qr[i*4+1] = fmaf(da[i*4+1], Qr[i*4+1], u * Bv.y);
            Qr[i*4+2] = fmaf(da[i*4+2], Qr[i*4+2], u * Bv.z);
            Qr[i*4+3] = fmaf(da[i*4+3], Qr[i*4+3], u * Bv.w);
            Pr[i*4+0] *= da[i*4+0];  Pr[i*4+1] *= da[i*4+1];
            Pr[i*4+2] *= da[i*4+2];  Pr[i*4+3] *= da[i*4+3];
        }
    }
    #pragma unroll
    for (int i = 0; i < 4; i++) {
        *(float4*)&P[cx.sumIdx + i*4] =
            make_float4(Pr[i*4], Pr[i*4+1], Pr[i*4+2], Pr[i*4+3]);
        *(float4*)&Q[cx.sumIdx + i*4] =
            make_float4(Qr[i*4], Qr[i*4+1], Qr[i*4+2], Qr[i*4+3]);
    }
}

__global__ void __launch_bounds__(128)
scanA_kernel(const float* __restrict__ xdbl, const float* __restrict__ xc,
             const float* __restrict__ W_dt, const float* __restrict__ b_dt,
             const float* __restrict__ A_log, const float* __restrict__ Dp,
             float* __restrict__ dt,
             float* __restrict__ P, float* __restrict__ Q)
{
    const int chunk = blockIdx.z;
    ChCtx cx = ch_setup(A_log, Dp, W_dt, b_dt, chunk);
    const float* pbc = xdbl + (long)cx.b*SEQ*48;
    const float* pxc = xc   + (long)cx.b*SEQ*D_INNER + cx.d;
    float*       pdt = dt   + (long)cx.b*SEQ*D_INNER + cx.d;
    const int t0 = chunk * CHUNK;
    if (cx.fast) phaseA_body<true >(cx, pbc, pxc, pdt, t0, P, Q);
    else         phaseA_body<false>(cx, pbc, pxc, pdt, t0, P, Q);
}

__global__ void __launch_bounds__(256)
scanB_kernel(const float* __restrict__ P, const float* __restrict__ Q,
             float* __restrict__ hin)
{
    int tid = blockIdx.x * 256 + threadIdx.x;
    if (tid >= BATCH * D_INNER * 4) return;
    int b  = tid / (D_INNER * 4);
    int r  = tid % (D_INNER * 4);
    int d  = r >> 2;
    int qg = r & 3;

    float4 h = make_float4(0.f, 0.f, 0.f, 0.f);
    #pragma unroll
    for (int c = 0; c < NC; c++) {
        long off = (((long)b*NC + c)*D_INNER + d)*16 + qg*4;
        *(float4*)&hin[off] = h;
        float4 Pv = *(const float4*)&P[off];
        float4 Qv = *(const float4*)&Q[off];
        h.x = fmaf(Pv.x, h.x, Qv.x);
        h.y = fmaf(Pv.y, h.y, Qv.y);
        h.z = fmaf(Pv.z, h.z, Qv.z);
        h.w = fmaf(Pv.w, h.w, Qv.w);
    }
}

template<bool FAST>
__device__ __forceinline__ void phaseC_body(
    const ChCtx& cx, const float* pbc, const float* pxc, const float* pz,
    const float* pdt, float* py, int t0, const float* hin)
{
    float h[16];
    #pragma unroll
    for (int i = 0; i < 4; i++) {
        float4 hv = *(const float4*)&hin[cx.sumIdx + i*4];
        h[i*4] = hv.x;  h[i*4+1] = hv.y;  h[i*4+2] = hv.z;  h[i*4+3] = hv.w;
    }

    #pragma unroll 2
    for (int t = t0; t < t0 + CHUNK; t++) {
        const float* row = pbc + (long)t * 48;
        float xcv = __ldg(pxc + (long)t * D_INNER);
        float zv  = __ldg(pz  + (long)t * 2 * D_INNER);
        float dtv = __ldg(pdt + (long)t * D_INNER);

        float da[16];
        if (FAST) da_tree(__expf(-dtv), da);
        else {
            #pragma unroll
            for (int n = 0; n < 16; n++) da[n] = __expf(dtv * cx.Av[n]);
        }

        float u = dtv * xcv;
        float p = 0.f;
        #pragma unroll
        for (int i = 0; i < 4; i++) {
            float4 Bv = __ldg((const float4*)(row + 16 + i*4));
            float4 Cv = __ldg((const float4*)(row + 32 + i*4));
            h[i*4+0] = fmaf(da[i*4+0], h[i*4+0], u * Bv.x);
            h[i*4+1] = fmaf(da[i*4+1], h[i*4+1], u * Bv.y);
            h[i*4+2] = fmaf(da[i*4+2], h[i*4+2], u * Bv.z);
            h[i*4+3] = fmaf(da[i*4+3], h[i*4+3], u * Bv.w);
            p = fmaf(h[i*4+0], Cv.x, p);
            p = fmaf(h[i*4+1], Cv.y, p);
            p = fmaf(h[i*4+2], Cv.z, p);
            p = fmaf(h[i*4+3], Cv.w, p);
        }

        float sil = zv / (1.f + __expf(-zv));
        py[(long)t * D_INNER] = (p + cx.Dval * xcv) * sil;
    }
}

__global__ void __launch_bounds__(128)
scanC_kernel(const float* __restrict__ xdbl, const float* __restrict__ xc,
             const float* __restrict__ xz, const float* __restrict__ dt,
             const float* __restrict__ W_dt, const float* __restrict__ b_dt,
             const float* __restrict__ A_log, const float* __restrict__ Dp,
             const float* __restrict__ hin, float* __restrict__ y)
{
    const int chunk = blockIdx.z;
    ChCtx cx = ch_setup(A_log, Dp, W_dt, b_dt, chunk);
    const float* pbc = xdbl + (long)cx.b*SEQ*48;
    const float* pxc = xc   + (long)cx.b*SEQ*D_INNER + cx.d;
    const float* pz  = xz   + (long)cx.b*SEQ*2*D_INNER + D_INNER + cx.d;
    const float* pdt = dt   + (long)cx.b*SEQ*D_INNER + cx.d;
    float*       py  = y    + (long)cx.b*SEQ*D_INNER + cx.d;
    const int t0 = chunk * CHUNK;
    if (cx.fast) phaseC_body<true >(cx, pbc, pxc, pz, pdt, py, t0, hin);
    else         phaseC_body<false>(cx, pbc, pxc, pz, pdt, py, t0, hin);
}

// ---------------- layernorm over D_MODEL=256 --------------------------------
__device__ __forceinline__ float block_sum256(float v, float* sm)
{
    #pragma unroll
    for (int o = 16; o; o >>= 1) v += __shfl_xor_sync(0xffffffffu, v, o);
    __syncthreads();
    if ((threadIdx.x & 31) == 0) sm[threadIdx.x >> 5] = v;
    __syncthreads();
    float tot = 0.f;
    #pragma unroll
    for (int j = 0; j < 8; j++) tot += sm[j];
    return tot;
}

__global__ void __launch_bounds__(256)
ln_kernel(const float* __restrict__ in, const float* __restrict__ g,
          const float* __restrict__ b, float* __restrict__ out)
{
    __shared__ float sm[8];
    const int row = blockIdx.x;
    const int i   = threadIdx.x;
    float v    = in[(long)row * D_MODEL + i];
    float mean = block_sum256(v, sm) * (1.f / D_MODEL);
    float dv   = v - mean;
    float var  = block_sum256(dv * dv, sm) * (1.f / D_MODEL);
    out[(long)row * D_MODEL + i] = dv * rsqrtf(var + 1e-5f) * g[i] + b[i];
}

// ---------------- mean pool over L + linear head -----------------------------
__global__ void __launch_bounds__(1024)
final_kernel(const float* __restrict__ h, const float* __restrict__ Wf,
             const float* __restrict__ bf, float* __restrict__ out)
{
    __shared__ float red[1024];
    __shared__ float sm[8];
    const int b   = blockIdx.x;
    const int tid = threadIdx.x;
    const int d   = tid & 255;
    const int lc  = tid >> 8;

    float s = 0.f;
    for (int l = lc * 256; l < (lc + 1) * 256; l++)
        s += h[((long)b * SEQ + l) * D_MODEL + d];
    red[tid] = s;
    __syncthreads();

    if (tid < 256) {
        float tot = red[tid] + red[tid + 256] + red[tid + 512] + red[tid + 768];
        float val = tot * (1.f / SEQ) * Wf[d];
        #pragma unroll
        for (int o = 16; o; o >>= 1) val += __shfl_xor_sync(0xffffffffu, val, o);
        if ((tid & 31) == 0) sm[tid >> 5] = val;
    }
    __syncthreads();
    if (tid == 0) {
        float tot = 0.f;
        #pragma unroll
        for (int j = 0; j < 8; j++) tot += sm[j];
        out[b] = tot + bf[0];
    }
}

// ---------------- host orchestration ----------------------------------------
extern "C" void kernel_launch(void* const* d_in, const int* in_sizes, int n_in,
                              void* d_out, int out_size)
{
    const float* x      = (const float*)d_in[0];
    const float* Wp     = (const float*)d_in[1];
    const float* bp     = (const float*)d_in[2];
    const float* W_in   = (const float*)d_in[3];
    const float* conv_w = (const float*)d_in[4];
    const float* conv_b = (const float*)d_in[5];
    const float* W_x    = (const float*)d_in[6];
    const float* W_dt   = (const float*)d_in[7];
    const float* b_dt   = (const float*)d_in[8];
    const float* A_log  = (const float*)d_in[9];
    const float* Dp     = (const float*)d_in[10];
    const float* W_out  = (const float*)d_in[11];
    const float* ln_g   = (const float*)d_in[12];
    const float* ln_b   = (const float*)d_in[13];
    const float* Wf     = (const float*)d_in[14];
    const float* bf     = (const float*)d_in[15];
    float* out = (float*)d_out;

    float *h, *xz, *xc, *xdbl, *xdp, *dtb, *y, *ob, *P, *Q, *hin;
    cudaGetSymbolAddress((void**)&h,    g_h);
    cudaGetSymbolAddress((void**)&xz,   g_xz);
    cudaGetSymbolAddress((void**)&xc,   g_xc);
    cudaGetSymbolAddress((void**)&xdbl, g_xdbl);
    cudaGetSymbolAddress((void**)&xdp,  g_xdp);
    cudaGetSymbolAddress((void**)&dtb,  g_dt);
    cudaGetSymbolAddress((void**)&y,    g_y);
    cudaGetSymbolAddress((void**)&ob,   g_ob);
    cudaGetSymbolAddress((void**)&P,    g_P);
    cudaGetSymbolAddress((void**)&Q,    g_q);
    cudaGetSymbolAddress((void**)&hin,  g_hin);

    // input projection: h = x @ Wp^T + bp   (M=8192, N=256, K=64)
    gemm_tc_kernel<true><<<dim3(D_MODEL/64, BL/128), 128>>>(
        x, IN_DIM, Wp, IN_DIM, bp, h, D_MODEL, BL, D_MODEL, IN_DIM);

    for (int l = 0; l < N_LAYERS; l++) {
        const float* Wi = W_in  + (long)l * 2*D_INNER * D_MODEL;
        const float* cw = conv_w + (long)l * D_INNER * D_CONV;
        const float* cb = conv_b + (long)l * D_INNER;
        const float* Wx = W_x   + (long)l * 48 * D_INNER;
        const float* Wd = W_dt  + (long)l * D_INNER * DT_RANK;
        const float* bd = b_dt  + (long)l * D_INNER;
        const float* Al = A_log + (long)l * D_INNER * D_STATE;
        const float* Dl = Dp    + (long)l * D_INNER;
        const float* Wo = W_out + (long)l * D_MODEL * D_INNER;
        const float* lg = ln_g  + (long)l * D_MODEL;
        const float* lb = ln_b  + (long)l * D_MODEL;

        // xz = h @ W_in^T   (M=8192, N=1024, K=256), 4-warp tc kernel
        gemm_tc_kernel<false><<<dim3(1024/64, BL/128), 128>>>(
            h, D_MODEL, Wi, D_MODEL, nullptr, xz, 2*D_INNER,
            BL, 2*D_INNER, D_MODEL);

        // xc = silu(conv(xh) + cb)
        conv_silu_kernel<<<BL*128/256, 256>>>(xz, cw, cb, xc);

        // x_dbl partials: split-K over 8 slices of 64 (f32x2 path)
        gemm4_kernel<32,64,16,4,4,true,true,4><<<dim3(1, BL/32, XD_KZ), 128>>>(
            xc, D_INNER, Wx, D_INNER, nullptr, xdp, 48,
            BL, 48, D_INNER / XD_KZ);
        reduceK_kernel<<<(BL*48/4 + 255)/256, 256>>>(xdp, xdbl, BL*48);

        // chunked selective scan, NC=32 (dt stored in A, loaded in C)
        scanA_kernel<<<dim3(D_INNER/128, BATCH, NC), 128>>>(
            xdbl, xc, Wd, bd, Al, Dl, dtb, P, Q);
        scanB_kernel<<<(BATCH*D_INNER*4 + 255)/256, 256>>>(P, Q, hin);
        scanC_kernel<<<dim3(D_INNER/128, BATCH, NC), 128>>>(
            xdbl, xc, xz, dtb, Wd, bd, Al, Dl, hin, y);

        // out = y @ W_out^T  (M=8192, N=256, K=512), 4-warp tc kernel
        gemm_tc_kernel<false><<<dim3(D_MODEL/64, BL/128), 128>>>(
            y, D_INNER, Wo, D_INNER, nullptr, ob, D_MODEL, BL, D_MODEL, D_INNER);

        // h = layernorm(out)
        ln_kernel<<<BL, 256>>>(ob, lg, lb, h);
    }

    final_kernel<<<BATCH, 1024>>>(h, Wf, bf, out);
}

// round 15
// speedup vs baseline: 1.1376x; 1.1376x over previous
#include <cuda_runtime.h>
#include <math.h>

#define BATCH   8
#define SEQ     1024
#define IN_DIM  64
#define D_MODEL 256
#define D_INNER 512
#define D_STATE 16
#define D_CONV  4
#define DT_RANK 16
#define N_LAYERS 4
#define BL (BATCH*SEQ)            // 8192 rows
#define XD_KZ 8                   // split-K factor for x_dbl
#define NC    16                  // time chunks for scan (proven optimum)
#define CHUNK (SEQ/NC)            // 64

// ---------------- scratch (static device globals; no runtime alloc) --------
__device__ float g_h   [BL * D_MODEL];
__device__ float g_xz  [BL * 2 * D_INNER];
__device__ float g_xc  [BL * D_INNER];
__device__ float g_xdbl[BL * 48];
__device__ float g_xdp [XD_KZ * BL * 48];
__device__ float g_dt  [BL * D_INNER];
__device__ float g_y   [BL * D_INNER];
__device__ float g_ob  [BL * D_MODEL];
__device__ float g_P   [BATCH * NC * D_INNER * D_STATE];
__device__ float g_q   [BATCH * NC * D_INNER * D_STATE];
__device__ float g_hin [BATCH * NC * D_INNER * D_STATE];

// ---------------- f32x2 helpers --------------------------------------------
__device__ __forceinline__ unsigned long long pk2dup(float a) {
    unsigned long long r;
    asm("mov.b64 %0, {%1, %1};" : "=l"(r) : "f"(a));
    return r;
}
__device__ __forceinline__ void fma2(unsigned long long& d,
                                     unsigned long long a, unsigned long long b) {
    asm("fma.rn.f32x2 %0, %1, %2, %0;" : "+l"(d) : "l"(a), "l"(b));
}
__device__ __forceinline__ float2 up2(unsigned long long v) {
    float2 o;
    asm("mov.b64 {%0, %1}, %2;" : "=f"(o.x), "=f"(o.y) : "l"(v));
    return o;
}

// ---------------- tf32 helpers ----------------------------------------------
__device__ __forceinline__ unsigned f2tf(float x) {
    unsigned r;
    asm("cvt.rna.tf32.f32 %0, %1;" : "=r"(r) : "f"(x));
    return r;
}
__device__ __forceinline__ void mma_tf32(float* c, const unsigned* a,
                                         const unsigned* b) {
    asm("mma.sync.aligned.m16n8k8.row.col.f32.tf32.tf32.f32 "
        "{%0,%1,%2,%3}, {%4,%5,%6,%7}, {%8,%9}, {%0,%1,%2,%3};"
        : "+f"(c[0]), "+f"(c[1]), "+f"(c[2]), "+f"(c[3])
        : "r"(a[0]), "r"(a[1]), "r"(a[2]), "r"(a[3]), "r"(b[0]), "r"(b[1]));
}

// ============================================================================
// Tensor-core NT GEMM, 4-warp (round-9 proven): BM=128 BN=64 BK=16.
// ============================================================================
template<bool BIAS>
__global__ void __launch_bounds__(128, 3)
gemm_tc_kernel(const float* __restrict__ A, int lda,
               const float* __restrict__ B, int ldb,
               const float* __restrict__ bias,
               float* __restrict__ C, int ldc,
               int M, int N, int K)
{
    constexpr int BM = 128, BN = 64, BK = 16, PAD = 4;

    __shared__ __align__(16) unsigned As[2][BM][BK + PAD];
    __shared__ __align__(16) unsigned Bs[2][BN][BK + PAD];

    const int tid  = threadIdx.x;
    const int lane = tid & 31;
    const int wid  = tid >> 5;
    const int g    = lane >> 2;
    const int tg   = lane & 3;
    const int mw   = (wid >> 1) * 64;
    const int nw   = (wid & 1) * 32;
    const int m0   = blockIdx.y * BM;
    const int n0   = blockIdx.x * BN;

    float acc[4][4][4];
    #pragma unroll
    for (int i = 0; i < 4; i++)
        #pragma unroll
        for (int j = 0; j < 4; j++)
            #pragma unroll
            for (int f = 0; f < 4; f++) acc[i][j][f] = 0.f;

    float4 vA[4], vB[2];

    auto loadA = [&](int k0) {
        #pragma unroll
        for (int i = 0; i < 4; i++) {
            int idx = tid + i * 128;
            int r = idx >> 2, cq = idx & 3;
            vA[i] = *(const float4*)&A[(long)(m0 + r) * lda + k0 + cq*4];
        }
    };
    auto loadB = [&](int k0) {
        #pragma unroll
        for (int i = 0; i < 2; i++) {
            int idx = tid + i * 128;
            int r = idx >> 2, cq = idx & 3;
            vB[i] = *(const float4*)&B[(long)(n0 + r) * ldb + k0 + cq*4];
        }
    };
    auto stage = [&](int s) {
        #pragma unroll
        for (int i = 0; i < 4; i++) {
            int idx = tid + i * 128;
            int r = idx >> 2, cq = idx & 3;
            uint4 t = make_uint4(f2tf(vA[i].x), f2tf(vA[i].y),
                                 f2tf(vA[i].z), f2tf(vA[i].w));
            *(uint4*)&As[s][r][cq*4] = t;
        }
        #pragma unroll
        for (int i = 0; i < 2; i++) {
            int idx = tid + i * 128;
            int r = idx >> 2, cq = idx & 3;
            uint4 t = make_uint4(f2tf(vB[i].x), f2tf(vB[i].y),
                                 f2tf(vB[i].z), f2tf(vB[i].w));
            *(uint4*)&Bs[s][r][cq*4] = t;
        }
    };

    loadA(0); loadB(0); stage(0);
    __syncthreads();

    int s = 0;
    for (int k0 = 0; k0 < K; k0 += BK) {
        bool has_next = (k0 + BK) < K;
        if (has_next) { loadA(k0 + BK); loadB(k0 + BK); }

        #pragma unroll
        for (int ks = 0; ks < BK; ks += 8) {
            unsigned a[4][4], b[4][2];
            #pragma unroll
            for (int mt = 0; mt < 4; mt++) {
                int rb = mw + mt * 16;
                a[mt][0] = As[s][rb + g    ][ks + tg    ];
                a[mt][1] = As[s][rb + g + 8][ks + tg    ];
                a[mt][2] = As[s][rb + g    ][ks + tg + 4];
                a[mt][3] = As[s][rb + g + 8][ks + tg + 4];
            }
            #pragma unroll
            for (int nt = 0; nt < 4; nt++) {
                int nb = nw + nt * 8;
                b[nt][0] = Bs[s][nb + g][ks + tg    ];
                b[nt][1] = Bs[s][nb + g][ks + tg + 4];
            }
            #pragma unroll
            for (int mt = 0; mt < 4; mt++)
                #pragma unroll
                for (int nt = 0; nt < 4; nt++)
                    mma_tf32(acc[mt][nt], a[mt], b[nt]);
        }

        if (has_next) {
            stage(s ^ 1);
            __syncthreads();
            s ^= 1;
        }
    }

    #pragma unroll
    for (int mt = 0; mt < 4; mt++) {
        #pragma unroll
        for (int nt = 0; nt < 4; nt++) {
            int m = m0 + mw + mt * 16 + g;
            int n = n0 + nw + nt * 8 + 2 * tg;
            float2 v0 = make_float2(acc[mt][nt][0], acc[mt][nt][1]);
            float2 v1 = make_float2(acc[mt][nt][2], acc[mt][nt][3]);
            if (BIAS) {
                float b0 = bias[n], b1 = bias[n+1];
                v0.x += b0;  v0.y += b1;
                v1.x += b0;  v1.y += b1;
            }
            *(float2*)&C[(long)m * ldc + n]       = v0;
            *(float2*)&C[(long)(m+8) * ldc + n]   = v1;
        }
    }
}

// ---------------- f32x2 GEMM (x_dbl split-K path, proven config) ------------
template<int BM, int BN, int BK, int TM, int TN, bool NG, bool SPLIT, int OCC>
__global__ void __launch_bounds__((BM/TM)*(BN/TN), OCC)
gemm4_kernel(const float* __restrict__ A, int lda,
             const float* __restrict__ B, int ldb,
             const float* __restrict__ bias,
             float* __restrict__ C, int ldc,
             int M, int N, int K)
{
    constexpr int THREADS = (BM/TM)*(BN/TN);
    constexpr int LAV = (BM*BK)/(4*THREADS);
    constexpr int LBV = (BN*BK)/(4*THREADS);
    static_assert(LAV >= 1 && LBV >= 1, "tile too small");

    if (SPLIT) {
        int z = blockIdx.z;
        A += (long)z * K;
        B += (long)z * K;
        C += (long)z * M * ldc;
    }

    __shared__ __align__(16) float As[2][BK][BM];
    __shared__ __align__(16) float Bs[2][BK][BN];

    const int tid = threadIdx.x;
    const int tx  = tid % (BN/TN);
    const int ty  = tid / (BN/TN);
    const int m0  = blockIdx.y * BM;
    const int n0  = blockIdx.x * BN;

    unsigned long long acc[TM][TN/2];
    #pragma unroll
    for (int i = 0; i < TM; i++)
        #pragma unroll
        for (int j = 0; j < TN/2; j++) acc[i][j] = 0ull;

    float4 vA[LAV], vB[LBV];

    auto loadA = [&](int k0) {
        #pragma unroll
        for (int i = 0; i < LAV; i++) {
            int idx = tid + i * THREADS;
            int r = idx / (BK/4), cq = idx % (BK/4);
            vA[i] = *(const float4*)&A[(long)(m0 + r) * lda + k0 + cq*4];
        }
    };
    auto loadB = [&](int k0) {
        #pragma unroll
        for (int i = 0; i < LBV; i++) {
            int idx = tid + i * THREADS;
            int r = idx / (BK/4), cq = idx % (BK/4);
            if (!NG || (n0 + r) < N)
                vB[i] = *(const float4*)&B[(long)(n0 + r) * ldb + k0 + cq*4];
            else
                vB[i] = make_float4(0.f, 0.f, 0.f, 0.f);
        }
    };
    auto stage = [&](int s) {
        #pragma unroll
        for (int i = 0; i < LAV; i++) {
            int idx = tid + i * THREADS;
            int r = idx / (BK/4), cq = idx % (BK/4);
            As[s][cq*4+0][r] = vA[i].x;  As[s][cq*4+1][r] = vA[i].y;
            As[s][cq*4+2][r] = vA[i].z;  As[s][cq*4+3][r] = vA[i].w;
        }
        #pragma unroll
        for (int i = 0; i < LBV; i++) {
            int idx = tid + i * THREADS;
            int r = idx / (BK/4), cq = idx % (BK/4);
            Bs[s][cq*4+0][r] = vB[i].x;  Bs[s][cq*4+1][r] = vB[i].y;
            Bs[s][cq*4+2][r] = vB[i].z;  Bs[s][cq*4+3][r] = vB[i].w;
        }
    };

    loadA(0); loadB(0); stage(0);
    __syncthreads();

    int s = 0;
    for (int k0 = 0; k0 < K; k0 += BK) {
        bool has_next = (k0 + BK) < K;
        if (has_next) { loadA(k0 + BK); loadB(k0 + BK); }

        #pragma unroll
        for (int kk = 0; kk < BK; kk++) {
            float a[TM];
            #pragma unroll
            for (int i = 0; i < TM; i += 4)
                *(float4*)&a[i] = *(const float4*)&As[s][kk][ty*TM + i];
            unsigned long long a2[TM];
            #pragma unroll
            for (int i = 0; i < TM; i++) a2[i] = pk2dup(a[i]);

            unsigned long long b2[TN/2];
            #pragma unroll
            for (int j = 0; j < TN/2; j += 2) {
                ulonglong2 tv = *(const ulonglong2*)&Bs[s][kk][tx*TN + 2*j];
                b2[j] = tv.x;  b2[j+1] = tv.y;
            }

            #pragma unroll
            for (int i = 0; i < TM; i++)
                #pragma unroll
                for (int j = 0; j < TN/2; j++)
                    fma2(acc[i][j], a2[i], b2[j]);
        }

        if (has_next) {
            stage(s ^ 1);
            __syncthreads();
            s ^= 1;
        }
    }

    #pragma unroll
    for (int i = 0; i < TM; i++) {
        int m = m0 + ty*TM + i;
        #pragma unroll
        for (int j = 0; j < TN/2; j++) {
            float2 v = up2(acc[i][j]);
            int n = n0 + tx*TN + 2*j;
            float x0 = v.x, x1 = v.y;
            if (bias) {
                if (!NG || n   < N) x0 += bias[n];
                if (!NG || n+1 < N) x1 += bias[n+1];
            }
            if (!NG || n   < N) C[(long)m*ldc + n  ] = x0;
            if (!NG || n+1 < N) C[(long)m*ldc + n+1] = x1;
        }
    }
}

// ---------------- split-K partial sum (XD_KZ -> 1), float4 ------------------
__global__ void __launch_bounds__(256)
reduceK_kernel(const float* __restrict__ in, float* __restrict__ out, int n)
{
    int i = (blockIdx.x * 256 + threadIdx.x) * 4;
    if (i >= n) return;
    float4 acc = make_float4(0.f, 0.f, 0.f, 0.f);
    #pragma unroll
    for (int z = 0; z < XD_KZ; z++) {
        float4 v = *(const float4*)&in[(long)z * n + i];
        acc.x += v.x;  acc.y += v.y;  acc.z += v.z;  acc.w += v.w;
    }
    *(float4*)&out[i] = acc;
}

// ---------------- conv+SiLU v2: 4 t-steps/thread, 7-row register window -----
// Bitwise-identical to v1: pre-sequence rows are zeros (a + 0*w == a exactly),
// per-output fma order over k unchanged.
__global__ void __launch_bounds__(256)
conv_silu_kernel(const float* __restrict__ xz,
                 const float* __restrict__ cw,
                 const float* __restrict__ cb,
                 float* __restrict__ xc)
{
    int idx = blockIdx.x * 256 + threadIdx.x;    // over (BL/4)*128
    int dq  = idx & 127;
    int blk = idx >> 7;
    int bl0 = blk * 4;                           // 4 consecutive rows, same seq
    int l0  = bl0 & (SEQ - 1);
    int b0  = bl0 - l0;
    int d   = dq * 4;

    float4 w0 = __ldg((const float4*)&cw[(d+0)*D_CONV]);
    float4 w1 = __ldg((const float4*)&cw[(d+1)*D_CONV]);
    float4 w2 = __ldg((const float4*)&cw[(d+2)*D_CONV]);
    float4 w3 = __ldg((const float4*)&cw[(d+3)*D_CONV]);
    float4 bv = __ldg((const float4*)&cb[d]);

    float4 xw[7];                                // rows l0-3 .. l0+3
    #pragma unroll
    for (int j = 0; j < 7; j++) {
        int ls = l0 - 3 + j;
        xw[j] = (ls >= 0)
            ? __ldg((const float4*)&xz[(long)(b0 + ls) * (2*D_INNER) + d])
            : make_float4(0.f, 0.f, 0.f, 0.f);
    }

    #pragma unroll
    for (int t = 0; t < 4; t++) {
        float a0 = bv.x, a1 = bv.y, a2 = bv.z, a3 = bv.w;
        #pragma unroll
        for (int k = 0; k < D_CONV; k++) {
            float4 xv = xw[t + k];
            a0 = fmaf(xv.x, (&w0.x)[k], a0);
            a1 = fmaf(xv.y, (&w1.x)[k], a1);
            a2 = fmaf(xv.z, (&w2.x)[k], a2);
            a3 = fmaf(xv.w, (&w3.x)[k], a3);
        }
        float4 o;
        o.x = a0 / (1.f + __expf(-a0));
        o.y = a1 / (1.f + __expf(-a1));
        o.z = a2 / (1.f + __expf(-a2));
        o.w = a3 / (1.f + __expf(-a3));
        *(float4*)&xc[(long)(bl0 + t) * D_INNER + d] = o;
    }
}

// ============================================================================
// Chunked selective scan (round-9 proven form), NC=16 chunks of 64 steps.
// One thread per channel; phase A stores dt, phase C loads it.
// ============================================================================

__device__ __forceinline__ void da_tree(float r, float* da)
{
    float r2  = r * r;
    float r4  = r2 * r2;
    float r8  = r4 * r4;
    float r12 = r8 * r4;
    float g0 = r, g1 = r2, g2 = r2 * r, g3 = r4;
    da[0] = g0;        da[1] = g1;        da[2] = g2;        da[3] = g3;
    da[4] = g0 * r4;   da[5] = g1 * r4;   da[6] = g2 * r4;   da[7] = g3 * r4;
    da[8] = g0 * r8;   da[9] = g1 * r8;   da[10] = g2 * r8;  da[11] = g3 * r8;
    da[12] = g0 * r12; da[13] = g1 * r12; da[14] = g2 * r12; da[15] = g3 * r12;
}

struct ChCtx {
    int b, d;
    float bdt, Dval;
    float4 w[4];
    float Av[16];
    long sumIdx;
    bool fast;
};

__device__ __forceinline__ ChCtx ch_setup(
    const float* A_log, const float* Dp,
    const float* W_dt, const float* b_dt, int chunk)
{
    ChCtx cx;
    cx.d = blockIdx.x * 128 + threadIdx.x;
    cx.b = blockIdx.y;
    bool ok = true;
    #pragma unroll
    for (int n = 0; n < 16; n++) {
        cx.Av[n] = -__expf(A_log[cx.d*D_STATE + n]);
        ok = ok && (fabsf(cx.Av[n] + (float)(n+1)) <= 1e-5f * (n+1));
    }
    cx.fast = __all_sync(0xffffffffu, ok);
    cx.Dval = Dp[cx.d];
    cx.bdt  = __ldg(&b_dt[cx.d]);
    #pragma unroll
    for (int i = 0; i < 4; i++)
        cx.w[i] = __ldg((const float4*)&W_dt[cx.d*DT_RANK + i*4]);
    cx.sumIdx = (((long)cx.b*NC + chunk)*D_INNER + cx.d)*16;
    return cx;
}

__device__ __forceinline__ float dot16_sp(const float* row, const ChCtx& cx)
{
    float s = cx.bdt;
    #pragma unroll
    for (int i = 0; i < 4; i++) {
        float4 dq = __ldg((const float4*)(row + i*4));
        s = fmaf(dq.x, cx.w[i].x, s);
        s = fmaf(dq.y, cx.w[i].y, s);
        s = fmaf(dq.z, cx.w[i].z, s);
        s = fmaf(dq.w, cx.w[i].w, s);
    }
    return (s > 20.f) ? s : __logf(1.f + __expf(s));
}

template<bool FAST>
__device__ __forceinline__ void phaseA_body(
    const ChCtx& cx, const float* pbc, const float* pxc, float* pdt,
    int t0, float* P, float* Q)
{
    float Pr[16], Qr[16];
    #pragma unroll
    for (int n = 0; n < 16; n++) { Pr[n] = 1.f; Qr[n] = 0.f; }

    #pragma unroll 2
    for (int t = t0; t < t0 + CHUNK; t++) {
        const float* row = pbc + (long)t * 48;
        float xcv = __ldg(pxc + (long)t * D_INNER);
        float dtv = dot16_sp(row, cx);
        pdt[(long)t * D_INNER] = dtv;

        float da[16];
        if (FAST) da_tree(__expf(-dtv), da);
        else {
            #pragma unroll
            for (int n = 0; n < 16; n++) da[n] = __expf(dtv * cx.Av[n]);
        }

        float u = dtv * xcv;
        #pragma unroll
        for (int i = 0; i < 4; i++) {
            float4 Bv = __ldg((const float4*)(row + 16 + i*4));
            Qr[i*4+0] = fmaf(da[i*4+0], Qr[i*4+0], u * Bv.x);
            Qr[i*4+1] = fmaf(da[i*4+1], Qr[i*4+1], u * Bv.y);
            Qr[i*4+2] = fmaf(da[i*4+2], Qr[i*4+2], u * Bv.z);
            Qr[i*4+3] = fmaf(da[i*4+3], Qr[i*4+3], u * Bv.w);
            Pr[i*4+0] *= da[i*4+0];  Pr[i*4+1] *= da[i*4+1];
            Pr[i*4+2] *= da[i*4+2];  Pr[i*4+3] *= da[i*4+3];
        }
    }
    #pragma unroll
    for (int i = 0; i < 4; i++) {
        *(float4*)&P[cx.sumIdx + i*4] =
            make_float4(Pr[i*4], Pr[i*4+1], Pr[i*4+2], Pr[i*4+3]);
        *(float4*)&Q[cx.sumIdx + i*4] =
            make_float4(Qr[i*4], Qr[i*4+1], Qr[i*4+2], Qr[i*4+3]);
    }
}

__global__ void __launch_bounds__(128)
scanA_kernel(const float* __restrict__ xdbl, const float* __restrict__ xc,
             const float* __restrict__ W_dt, const float* __restrict__ b_dt,
             const float* __restrict__ A_log, const float* __restrict__ Dp,
             float* __restrict__ dt,
             float* __restrict__ P, float* __restrict__ Q)
{
    const int chunk = blockIdx.z;
    ChCtx cx = ch_setup(A_log, Dp, W_dt, b_dt, chunk);
    const float* pbc = xdbl + (long)cx.b*SEQ*48;
    const float* pxc = xc   + (long)cx.b*SEQ*D_INNER + cx.d;
    float*       pdt = dt   + (long)cx.b*SEQ*D_INNER + cx.d;
    const int t0 = chunk * CHUNK;
    if (cx.fast) phaseA_body<true >(cx, pbc, pxc, pdt, t0, P, Q);
    else         phaseA_body<false>(cx, pbc, pxc, pdt, t0, P, Q);
}

__global__ void __launch_bounds__(256)
scanB_kernel(const float* __restrict__ P, const float* __restrict__ Q,
             float* __restrict__ hin)
{
    int tid = blockIdx.x * 256 + threadIdx.x;
    if (tid >= BATCH * D_INNER * 4) return;
    int b  = tid / (D_INNER * 4);
    int r  = tid % (D_INNER * 4);
    int d  = r >> 2;
    int qg = r & 3;

    float4 h = make_float4(0.f, 0.f, 0.f, 0.f);
    #pragma unroll
    for (int c = 0; c < NC; c++) {
        long off = (((long)b*NC + c)*D_INNER + d)*16 + qg*4;
        *(float4*)&hin[off] = h;
        float4 Pv = *(const float4*)&P[off];
        float4 Qv = *(const float4*)&Q[off];
        h.x = fmaf(Pv.x, h.x, Qv.x);
        h.y = fmaf(Pv.y, h.y, Qv.y);
        h.z = fmaf(Pv.z, h.z, Qv.z);
        h.w = fmaf(Pv.w, h.w, Qv.w);
    }
}

template<bool FAST>
__device__ __forceinline__ void phaseC_body(
    const ChCtx& cx, const float* pbc, const float* pxc, const float* pz,
    const float* pdt, float* py, int t0, const float* hin)
{
    float h[16];
    #pragma unroll
    for (int i = 0; i < 4; i++) {
        float4 hv = *(const float4*)&hin[cx.sumIdx + i*4];
        h[i*4] = hv.x;  h[i*4+1] = hv.y;  h[i*4+2] = hv.z;  h[i*4+3] = hv.w;
    }

    #pragma unroll 2
    for (int t = t0; t < t0 + CHUNK; t++) {
        const float* row = pbc + (long)t * 48;
        float xcv = __ldg(pxc + (long)t * D_INNER);
        float zv  = __ldg(pz  + (long)t * 2 * D_INNER);
        float dtv = __ldg(pdt + (long)t * D_INNER);

        float da[16];
        if (FAST) da_tree(__expf(-dtv), da);
        else {
            #pragma unroll
            for (int n = 0; n < 16; n++) da[n] = __expf(dtv * cx.Av[n]);
        }

        float u = dtv * xcv;
        float p = 0.f;
        #pragma unroll
        for (int i = 0; i < 4; i++) {
            float4 Bv = __ldg((const float4*)(row + 16 + i*4));
            float4 Cv = __ldg((const float4*)(row + 32 + i*4));
            h[i*4+0] = fmaf(da[i*4+0], h[i*4+0], u * Bv.x);
            h[i*4+1] = fmaf(da[i*4+1], h[i*4+1], u * Bv.y);
            h[i*4+2] = fmaf(da[i*4+2], h[i*4+2], u * Bv.z);
            h[i*4+3] = fmaf(da[i*4+3], h[i*4+3], u * Bv.w);
            p = fmaf(h[i*4+0], Cv.x, p);
            p = fmaf(h[i*4+1], Cv.y, p);
            p = fmaf(h[i*4+2], Cv.z, p);
            p = fmaf(h[i*4+3], Cv.w, p);
        }

        float sil = zv / (1.f + __expf(-zv));
        py[(long)t * D_INNER] = (p + cx.Dval * xcv) * sil;
    }
}

__global__ void __launch_bounds__(128)
scanC_kernel(const float* __restrict__ xdbl, const float* __restrict__ xc,
             const float* __restrict__ xz, const float* __restrict__ dt,
             const float* __restrict__ W_dt, const float* __restrict__ b_dt,
             const float* __restrict__ A_log, const float* __restrict__ Dp,
             const float* __restrict__ hin, float* __restrict__ y)
{
    const int chunk = blockIdx.z;
    ChCtx cx = ch_setup(A_log, Dp, W_dt, b_dt, chunk);
    const float* pbc = xdbl + (long)cx.b*SEQ*48;
    const float* pxc = xc   + (long)cx.b*SEQ*D_INNER + cx.d;
    const float* pz  = xz   + (long)cx.b*SEQ*2*D_INNER + D_INNER + cx.d;
    const float* pdt = dt   + (long)cx.b*SEQ*D_INNER + cx.d;
    float*       py  = y    + (long)cx.b*SEQ*D_INNER + cx.d;
    const int t0 = chunk * CHUNK;
    if (cx.fast) phaseC_body<true >(cx, pbc, pxc, pz, pdt, py, t0, hin);
    else         phaseC_body<false>(cx, pbc, pxc, pz, pdt, py, t0, hin);
}

// ---------------- layernorm v2: warp-per-row (8 rows / 256-thr block) -------
__global__ void __launch_bounds__(256)
ln_kernel(const float* __restrict__ in, const float* __restrict__ g,
          const float* __restrict__ b, float* __restrict__ out)
{
    const int row  = blockIdx.x * 8 + (threadIdx.x >> 5);
    const int lane = threadIdx.x & 31;
    const long base = (long)row * D_MODEL + lane * 8;

    float4 v0 = *(const float4*)&in[base];
    float4 v1 = *(const float4*)&in[base + 4];

    float s = ((v0.x + v0.y) + (v0.z + v0.w)) +
              ((v1.x + v1.y) + (v1.z + v1.w));
    #pragma unroll
    for (int o = 16; o; o >>= 1) s += __shfl_xor_sync(0xffffffffu, s, o);
    float mean = s * (1.f / D_MODEL);

    float d0 = v0.x - mean, d1 = v0.y - mean, d2 = v0.z - mean, d3 = v0.w - mean;
    float d4 = v1.x - mean, d5 = v1.y - mean, d6 = v1.z - mean, d7 = v1.w - mean;

    float q = ((d0*d0 + d1*d1) + (d2*d2 + d3*d3)) +
              ((d4*d4 + d5*d5) + (d6*d6 + d7*d7));
    #pragma unroll
    for (int o = 16; o; o >>= 1) q += __shfl_xor_sync(0xffffffffu, q, o);
    float rstd = rsqrtf(q * (1.f / D_MODEL) + 1e-5f);

    float4 g0 = *(const float4*)&g[lane*8];
    float4 g1 = *(const float4*)&g[lane*8 + 4];
    float4 b0 = *(const float4*)&b[lane*8];
    float4 b1 = *(const float4*)&b[lane*8 + 4];

    float4 o0, o1;
    o0.x = d0 * rstd * g0.x + b0.x;  o0.y = d1 * rstd * g0.y + b0.y;
    o0.z = d2 * rstd * g0.z + b0.z;  o0.w = d3 * rstd * g0.w + b0.w;
    o1.x = d4 * rstd * g1.x + b1.x;  o1.y = d5 * rstd * g1.y + b1.y;
    o1.z = d6 * rstd * g1.z + b1.z;  o1.w = d7 * rstd * g1.w + b1.w;

    *(float4*)&out[base]     = o0;
    *(float4*)&out[base + 4] = o1;
}

// ---------------- mean pool over L + linear head -----------------------------
__global__ void __launch_bounds__(1024)
final_kernel(const float* __restrict__ h, const float* __restrict__ Wf,
             const float* __restrict__ bf, float* __restrict__ out)
{
    __shared__ float red[1024];
    __shared__ float sm[8];
    const int b   = blockIdx.x;
    const int tid = threadIdx.x;
    const int d   = tid & 255;
    const int lc  = tid >> 8;

    float s = 0.f;
    for (int l = lc * 256; l < (lc + 1) * 256; l++)
        s += h[((long)b * SEQ + l) * D_MODEL + d];
    red[tid] = s;
    __syncthreads();

    if (tid < 256) {
        float tot = red[tid] + red[tid + 256] + red[tid + 512] + red[tid + 768];
        float val = tot * (1.f / SEQ) * Wf[d];
        #pragma unroll
        for (int o = 16; o; o >>= 1) val += __shfl_xor_sync(0xffffffffu, val, o);
        if ((tid & 31) == 0) sm[tid >> 5] = val;
    }
    __syncthreads();
    if (tid == 0) {
        float tot = 0.f;
        #pragma unroll
        for (int j = 0; j < 8; j++) tot += sm[j];
        out[b] = tot + bf[0];
    }
}

// ---------------- host orchestration ----------------------------------------
extern "C" void kernel_launch(void* const* d_in, const int* in_sizes, int n_in,
                              void* d_out, int out_size)
{
    const float* x      = (const float*)d_in[0];
    const float* Wp     = (const float*)d_in[1];
    const float* bp     = (const float*)d_in[2];
    const float* W_in   = (const float*)d_in[3];
    const float* conv_w = (const float*)d_in[4];
    const float* conv_b = (const float*)d_in[5];
    const float* W_x    = (const float*)d_in[6];
    const float* W_dt   = (const float*)d_in[7];
    const float* b_dt   = (const float*)d_in[8];
    const float* A_log  = (const float*)d_in[9];
    const float* Dp     = (const float*)d_in[10];
    const float* W_out  = (const float*)d_in[11];
    const float* ln_g   = (const float*)d_in[12];
    const float* ln_b   = (const float*)d_in[13];
    const float* Wf     = (const float*)d_in[14];
    const float* bf     = (const float*)d_in[15];
    float* out = (float*)d_out;

    float *h, *xz, *xc, *xdbl, *xdp, *dtb, *y, *ob, *P, *Q, *hin;
    cudaGetSymbolAddress((void**)&h,    g_h);
    cudaGetSymbolAddress((void**)&xz,   g_xz);
    cudaGetSymbolAddress((void**)&xc,   g_xc);
    cudaGetSymbolAddress((void**)&xdbl, g_xdbl);
    cudaGetSymbolAddress((void**)&xdp,  g_xdp);
    cudaGetSymbolAddress((void**)&dtb,  g_dt);
    cudaGetSymbolAddress((void**)&y,    g_y);
    cudaGetSymbolAddress((void**)&ob,   g_ob);
    cudaGetSymbolAddress((void**)&P,    g_P);
    cudaGetSymbolAddress((void**)&Q,    g_q);
    cudaGetSymbolAddress((void**)&hin,  g_hin);

    // input projection: h = x @ Wp^T + bp   (M=8192, N=256, K=64)
    gemm_tc_kernel<true><<<dim3(D_MODEL/64, BL/128), 128>>>(
        x, IN_DIM, Wp, IN_DIM, bp, h, D_MODEL, BL, D_MODEL, IN_DIM);

    for (int l = 0; l < N_LAYERS; l++) {
        const float* Wi = W_in  + (long)l * 2*D_INNER * D_MODEL;
        const float* cw = conv_w + (long)l * D_INNER * D_CONV;
        const float* cb = conv_b + (long)l * D_INNER;
        const float* Wx = W_x   + (long)l * 48 * D_INNER;
        const float* Wd = W_dt  + (long)l * D_INNER * DT_RANK;
        const float* bd = b_dt  + (long)l * D_INNER;
        const float* Al = A_log + (long)l * D_INNER * D_STATE;
        const float* Dl = Dp    + (long)l * D_INNER;
        const float* Wo = W_out + (long)l * D_MODEL * D_INNER;
        const float* lg = ln_g  + (long)l * D_MODEL;
        const float* lb = ln_b  + (long)l * D_MODEL;

        // xz = h @ W_in^T   (M=8192, N=1024, K=256), 4-warp tc kernel
        gemm_tc_kernel<false><<<dim3(1024/64, BL/128), 128>>>(
            h, D_MODEL, Wi, D_MODEL, nullptr, xz, 2*D_INNER,
            BL, 2*D_INNER, D_MODEL);

        // xc = silu(conv(xh) + cb), 4 t/thread windowed
        conv_silu_kernel<<<(BL/4)*128/256, 256>>>(xz, cw, cb, xc);

        // x_dbl partials: split-K over 8 slices of 64 (f32x2 path)
        gemm4_kernel<32,64,16,4,4,true,true,4><<<dim3(1, BL/32, XD_KZ), 128>>>(
            xc, D_INNER, Wx, D_INNER, nullptr, xdp, 48,
            BL, 48, D_INNER / XD_KZ);
        reduceK_kernel<<<(BL*48/4 + 255)/256, 256>>>(xdp, xdbl, BL*48);

        // chunked selective scan, NC=16 (dt stored in A, loaded in C)
        scanA_kernel<<<dim3(D_INNER/128, BATCH, NC), 128>>>(
            xdbl, xc, Wd, bd, Al, Dl, dtb, P, Q);
        scanB_kernel<<<(BATCH*D_INNER*4 + 255)/256, 256>>>(P, Q, hin);
        scanC_kernel<<<dim3(D_INNER/128, BATCH, NC), 128>>>(
            xdbl, xc, xz, dtb, Wd, bd, Al, Dl, hin, y);

        // out = y @ W_out^T  (M=8192, N=256, K=512), 4-warp tc kernel
        gemm_tc_kernel<false><<<dim3(D_MODEL/64, BL/128), 128>>>(
            y, D_INNER, Wo, D_INNER, nullptr, ob, D_MODEL, BL, D_MODEL, D_INNER);

        // h = layernorm(out), warp-per-row
        ln_kernel<<<BL/8, 256>>>(ob, lg, lb, h);
    }

    final_kernel<<<BATCH, 1024>>>(h, Wf, bf, out);
}